// round 14
// baseline (speedup 1.0000x reference)
#include <cuda_runtime.h>
#include <math.h>

// SpectralAngleLoss R14: proven block-per-row smem-atomic body (ATOMS ceiling).
// Tail: ONE fire-and-forget 64-bit RED.ADD per CTA carrying packed
// {count (bits 48+), fixed-point angle sum (low 48, angle*2^28)} — no return
// consumed, no fence, no per-CTA stall. The last-scheduled CTA's tid0 polls the
// packed word until count==rows, then finalizes, writes out, resets.

#define N_PEAKS   256
#define NUM_BINS  2000
#define NB_PAD    2048
#define MAX_ROWS  8192
#define THREADS   256

#define FIXED_SCALE 268435456.0f            // 2^28
#define COUNT_ONE   (1ULL << 48)
#define SUM_MASK    ((1ULL << 48) - 1ULL)

__device__ unsigned long long g_pack = 0ULL;   // reset by finisher each replay

__device__ __forceinline__ int mz_bin(float mz) {
    int b = (int)(mz * 2000.0f);           // trunc toward zero == astype(int32)
    return min(max(b, 0), NUM_BINS - 1);
}

__global__ __launch_bounds__(THREADS)
void sal_row(const float* __restrict__ pred_mz,
             const float* __restrict__ pred_int,
             const float* __restrict__ targ_mz,
             const float* __restrict__ targ_int,
             const float* __restrict__ targ_mask,
             float* __restrict__ out, int rows)
{
    __shared__ __align__(16) float ph[NB_PAD];
    __shared__ __align__(16) float th[NB_PAD];
    __shared__ float red[3][THREADS / 32];

    const int row = blockIdx.x;
    const int tid = threadIdx.x;

    // ---- zero both histograms (2 STS.128 per thread per array, exact)
    {
        float4 z = make_float4(0.f, 0.f, 0.f, 0.f);
        float4* p4 = (float4*)ph;
        float4* t4 = (float4*)th;
        #pragma unroll
        for (int i = 0; i < NB_PAD / 4 / THREADS; i++) {   // 2 iters
            p4[tid + i * THREADS] = z;
            t4[tid + i * THREADS] = z;
        }
    }

    // ---- coalesced loads, one element per thread
    const int idx = row * N_PEAKS + tid;
    const float ip  = pred_int[idx];
    const float itm = targ_int[idx] * targ_mask[idx];
    const int   bp  = mz_bin(pred_mz[idx]);
    const int   bt  = mz_bin(targ_mz[idx]);
    __syncthreads();

    // ---- scatter: 2 spread smem atomics per thread (the hardware floor)
    atomicAdd(&ph[bp], ip);
    atomicAdd(&th[bt], itm);
    __syncthreads();

    // ---- gather-form reductions: 3 LDS per thread, no bin scan
    float dot = ip  * th[bp];
    float pn  = ip  * ph[bp];
    float tn  = itm * th[bt];

    #pragma unroll
    for (int o = 16; o > 0; o >>= 1) {
        dot += __shfl_xor_sync(0xFFFFFFFFu, dot, o);
        pn  += __shfl_xor_sync(0xFFFFFFFFu, pn,  o);
        tn  += __shfl_xor_sync(0xFFFFFFFFu, tn,  o);
    }
    if ((tid & 31) == 0) {
        int w = tid >> 5;
        red[0][w] = dot; red[1][w] = pn; red[2][w] = tn;
    }
    __syncthreads();

    if (tid == 0) {
        float d = 0.f, a = 0.f, b = 0.f;
        #pragma unroll
        for (int w = 0; w < THREADS / 32; w++) {
            d += red[0][w]; a += red[1][w]; b += red[2][w];
        }
        const float eps = 1e-8f;
        float c = d / (fmaxf(sqrtf(a), eps) * fmaxf(sqrtf(b), eps));
        c = fminf(fmaxf(c, -1.0f), 1.0f);
        float angle = acosf(c);

        // ---- fire-and-forget packed contribution: return NOT consumed -> RED
        unsigned long long contrib =
            (unsigned long long)(angle * FIXED_SCALE + 0.5f) + COUNT_ONE;
        atomicAdd(&g_pack, contrib);       // no old value used: no stall

        // ---- designated finisher: last-scheduled CTA polls for completion
        if (blockIdx.x == (unsigned)(rows - 1)) {
            unsigned long long pack;
            while (((pack = atomicAdd(&g_pack, 0ULL)) >> 48)
                       < (unsigned long long)rows) {
                __nanosleep(256);
            }
            double total = (double)(pack & SUM_MASK) / (double)FIXED_SCALE;
            out[0] = (float)(total / ((double)rows * 3.141592653589793));
            atomicExch(&g_pack, 0ULL);     // reset for next graph replay
        }
    }
}

extern "C" void kernel_launch(void* const* d_in, const int* in_sizes, int n_in,
                              void* d_out, int out_size)
{
    const float* pred_mz   = (const float*)d_in[0];
    const float* pred_int  = (const float*)d_in[1];
    const float* targ_mz   = (const float*)d_in[2];
    const float* targ_int  = (const float*)d_in[3];
    const float* targ_mask = (const float*)d_in[4];
    float* out = (float*)d_out;

    int rows = in_sizes[0] / N_PEAKS;
    if (rows > MAX_ROWS) rows = MAX_ROWS;

    sal_row<<<rows, THREADS>>>(pred_mz, pred_int, targ_mz, targ_int,
                               targ_mask, out, rows);
}